// round 9
// baseline (speedup 1.0000x reference)
#include <cuda_runtime.h>
#include <cstdint>

#define BB   32
#define NN   25200
#define NCH  85
#define NCL  80
#define KNMS 4096
#define CONF_T 0.25f
#define IOU_T  0.45f
#define MAXDET 1000
#define MAXWH  7680.0f
#define CLCAP 256
#define FULLM 0xffffffffu
#define RPB  256           // rows per k_all block (= 8 mask words)
#define NWORDS 788         // ceil(25200/32)
#define NPART 8            // accumulation partials per image

__device__ unsigned g_maskA[BB * NWORDS];    // xc bitmask
__device__ unsigned g_maskW[BB * NWORDS];    // w bitmask
__device__ float         g_conf[BB * NN];    // by row (w rows)
__device__ unsigned char g_j[BB * NN];       // by row (w rows)
__device__ float4        g_cbox[BB * NN];    // by row (w rows)

__device__ unsigned short g_A16[BB * KNMS];       // xc rank -> row
__device__ unsigned long long g_keys[BB * KNMS];  // by w-rank m
__device__ float4        g_box[BB * KNMS];        // by w-rank m
__device__ unsigned short g_cls[BB * NCL * CLCAP];// per-class m lists
__device__ int           g_clsn[BB * NCL];
__device__ unsigned char g_kem[BB * KNMS];        // kept flag by m
__device__ int           g_kept[BB];
__device__ int           g_cw[BB];                // C per image
__device__ unsigned short g_pickrow[BB * MAXDET]; // picked rows (A[m])
__device__ int           g_cnt[BB];
__device__ float         g_part[BB * NPART * NCL];

// ---------------- K1: full-grid row scan + candidate scoring -> bitmasks ----------------
__global__ void k_all(const float* __restrict__ p) {
    int b = blockIdx.y;
    int r0 = blockIdx.x * RPB;
    int tid = threadIdx.x, lane = tid & 31, wid = tid >> 5;
    __shared__ unsigned short wl[RPB];
    __shared__ unsigned sm_wmask[RPB / 32];
    __shared__ int s_cnt;
    if (tid == 0) s_cnt = 0;
    if (tid < RPB / 32) sm_wmask[tid] = 0u;
    __syncthreads();

    int row = r0 + tid;
    bool xc = false;
    if (row < NN) {
        float obj = p[((size_t)b * NN + row) * NCH + 4];
        xc = obj > CONF_T;
    }
    unsigned bal = __ballot_sync(FULLM, xc);
    if (lane == 0 && row < NN)
        g_maskA[b * NWORDS + (row >> 5)] = bal;
    int base = 0;
    if (lane == 0 && bal) base = atomicAdd(&s_cnt, __popc(bal));
    base = __shfl_sync(FULLM, base, 0);
    if (xc) wl[base + __popc(bal & ((1u << lane) - 1u))] = (unsigned short)row;
    __syncthreads();

    int cnt = s_cnt;
    for (int k = wid; k < cnt; k += 8) {
        int r = wl[k];
        const float* pr = p + ((size_t)b * NN + r) * NCH;
        float v0 = pr[lane];
        float v1 = pr[lane + 32];
        float v2 = (lane < 21) ? pr[lane + 64] : 0.0f;
        float obj = __shfl_sync(FULLM, v0, 4);

        float bv = -3.4e38f; int bi = 1 << 20;
        if (lane >= 5) { bv = obj * v0; bi = lane - 5; }          // cls 0..26
        { float sc = obj * v1; int i1 = lane + 27;                // cls 27..58
          if (sc > bv) { bv = sc; bi = i1; } }
        if (lane < 21) { float sc = obj * v2; int i2 = lane + 59; // cls 59..79
          if (sc > bv) { bv = sc; bi = i2; } }
        for (int off = 16; off; off >>= 1) {
            float ov = __shfl_xor_sync(FULLM, bv, off);
            int   oi = __shfl_xor_sync(FULLM, bi, off);
            if (ov > bv || (ov == bv && oi < bi)) { bv = ov; bi = oi; }
        }
        float x  = __shfl_sync(FULLM, v0, 0);
        float y  = __shfl_sync(FULLM, v0, 1);
        float ww = __shfl_sync(FULLM, v0, 2);
        float hh = __shfl_sync(FULLM, v0, 3);
        if (lane == 0 && bv > CONF_T) {
            atomicOr(&sm_wmask[(r - r0) >> 5], 1u << (r & 31));
            g_conf[b * NN + r] = bv;
            g_j[b * NN + r] = (unsigned char)bi;
            float off = (float)bi * MAXWH;
            float hw = __fmul_rn(ww, 0.5f);
            float hv = __fmul_rn(hh, 0.5f);
            float4 bx;
            bx.x = __fadd_rn(__fsub_rn(x, hw), off);
            bx.y = __fadd_rn(__fsub_rn(y, hv), off);
            bx.z = __fadd_rn(__fadd_rn(x, hw), off);
            bx.w = __fadd_rn(__fadd_rn(y, hv), off);
            g_cbox[b * NN + r] = bx;
        }
    }
    __syncthreads();
    if (tid < RPB / 32) {
        int word = (r0 >> 5) + tid;
        if (word < NWORDS && word * 32 < NN)
            g_maskW[b * NWORDS + word] = sm_wmask[tid];
    }
}

// ---------------- K2: per-image prep: scan + scatter + class bucketing ----------------
__global__ void k_prep() {
    int b = blockIdx.x;
    int tid = threadIdx.x, lane = tid & 31, wid = tid >> 5;
    __shared__ int wsum[32];
    __shared__ int s_total;
    __shared__ int clsCnt[NCL];

    unsigned wa = 0, wb = 0;
    if (tid < NWORDS) {
        wa = g_maskA[b * NWORDS + tid];
        wb = g_maskW[b * NWORDS + tid];
    }
    if (tid < NCL) clsCnt[tid] = 0;
    if (tid == 0) g_kept[b] = 0;
    ((int*)(g_kem + (size_t)b * KNMS))[tid] = 0;
    int pk = __popc(wa) | (__popc(wb) << 16);
    int s = pk;
    for (int o = 1; o < 32; o <<= 1) {
        int v = __shfl_up_sync(FULLM, s, o);
        if (lane >= o) s += v;
    }
    if (lane == 31) wsum[wid] = s;
    __syncthreads();
    if (wid == 0) {
        int w = wsum[lane];
        for (int o = 1; o < 32; o <<= 1) {
            int v = __shfl_up_sync(FULLM, w, o);
            if (lane >= o) w += v;
        }
        wsum[lane] = w;
        if (lane == 31) s_total = w;
    }
    __syncthreads();
    int excl = (wid ? wsum[wid - 1] : 0) + s - pk;
    {
        int pa = excl & 0xffff;
        unsigned w = wa;
        while (w) {
            int bit = __ffs(w) - 1; w &= w - 1;
            if (pa < KNMS) g_A16[b * KNMS + pa] = (unsigned short)(tid * 32 + bit);
            pa++;
        }
        int pw = excl >> 16;
        w = wb;
        while (w) {
            int bit = __ffs(w) - 1; w &= w - 1;
            int r = tid * 32 + bit;
            if (pw < KNMS) {
                g_keys[b * KNMS + pw] =
                    ((unsigned long long)__float_as_uint(g_conf[b * NN + r]) << 32)
                  | (unsigned long long)(~(unsigned)pw);
                g_box[b * KNMS + pw] = g_cbox[b * NN + r];
                int c = g_j[b * NN + r];
                int slot = atomicAdd(&clsCnt[c], 1);
                if (slot < CLCAP)
                    g_cls[((size_t)b * NCL + c) * CLCAP + slot] = (unsigned short)pw;
            }
            pw++;
        }
    }
    __syncthreads();
    if (tid == 0) {
        int C = s_total >> 16; if (C > KNMS) C = KNMS;
        g_cw[b] = C;
    }
    if (tid < NCL) {
        int n = clsCnt[tid]; if (n > CLCAP) n = CLCAP;
        g_clsn[b * NCL + tid] = n;
    }
}

// ---------------- K3: one warp per (image, class) greedy NMS ----------------
// Classes never overlap (offset 7680 >> box extent): cross-class IoU == 0.
__global__ void k_greedy() {
    int b = blockIdx.y;
    int tid = threadIdx.x, lane = tid & 31, wid = tid >> 5;
    int c = blockIdx.x * 8 + wid;

    extern __shared__ char smem[];
    char* wbase = smem + wid * 8192;
    unsigned long long* sk = (unsigned long long*)(wbase + 0);    // 256*8
    float4*         sbx = (float4*)(wbase + 2048);                // 256*16
    float*          sar = (float*)(wbase + 6144);                 // 256*4
    unsigned short* sml = (unsigned short*)(wbase + 7168);        // 256*2
    unsigned short* dst = (unsigned short*)(wbase + 7680);        // 256*2

    if (c >= NCL) return;
    int n = g_clsn[b * NCL + c];
    if (n == 0) return;

    for (int e = lane; e < n; e += 32) {
        int m = g_cls[((size_t)b * NCL + c) * CLCAP + e];
        sml[e] = (unsigned short)m;
        sk[e] = g_keys[b * KNMS + m];
        float4 bx = g_box[b * KNMS + m];
        sbx[e] = bx;
        sar[e] = __fmul_rn(__fsub_rn(bx.z, bx.x), __fsub_rn(bx.w, bx.y));
    }
    __syncwarp();
    // rank-sort descending by key (keys unique -> perfect permutation)
    for (int e = lane; e < n; e += 32) {
        unsigned long long ke = sk[e];
        int r = 0;
        for (int f = 0; f < n; f++) r += (sk[f] > ke) ? 1 : 0;
        dst[r] = (unsigned short)e;
    }
    __syncwarp();

    int kcnt = 0;
    unsigned rm = 0;   // removed: entry e owned by lane e&31, bit e>>5
    for (int i = 0; i < n; i++) {
        unsigned rmi = __shfl_sync(FULLM, rm, i & 31);
        if ((rmi >> (i >> 5)) & 1u) continue;   // uniform
        int mi = dst[i];
        kcnt++;
        if (lane == 0) g_kem[b * KNMS + sml[mi]] = 1;
        float4 bi4 = sbx[mi];
        float ba = sar[mi];
        for (int k = 0, e = lane; e < n; k++, e += 32) {
            if (e > i && !((rm >> k) & 1u)) {
                int mj = dst[e];
                float4 bj = sbx[mj];
                float iw = __fsub_rn(fminf(bj.z, bi4.z), fmaxf(bj.x, bi4.x));
                float ih = __fsub_rn(fminf(bj.w, bi4.w), fmaxf(bj.y, bi4.y));
                float inter = __fmul_rn(fmaxf(iw, 0.0f), fmaxf(ih, 0.0f));
                float denom = __fsub_rn(__fadd_rn(sar[mj], ba), inter);
                if (__fdiv_rn(inter, denom) > IOU_T) rm |= (1u << k);
            }
        }
        __syncwarp();
    }
    if (lane == 0 && kcnt) atomicAdd(&g_kept[b], kcnt);
}

// ---------------- K4: radix select + cap -> pick rows ----------------
__global__ void k_select() {
    int b = blockIdx.x;
    int tid = threadIdx.x, lane = tid & 31, wid = tid >> 5;

    extern __shared__ char smem[];
    unsigned long long* keys = (unsigned long long*)(smem + 0);    // 32KB
    int*            picks = (int*)(smem + 32768);                  // 4KB
    unsigned char*  kem   = (unsigned char*)(smem + 36864);        // 4KB
    __shared__ int wsum[32];
    __shared__ int hist[256];
    __shared__ int s_total, s_target;
    __shared__ unsigned long long s_pre;

    int C = g_cw[b];
    int keptTotal = g_kept[b];
    for (int t = tid; t < KNMS; t += 1024) {
        keys[t] = (t < C) ? g_keys[b * KNMS + t] : 0ull;
        kem[t]  = (t < C) ? g_kem[b * KNMS + t] : 0;
    }
    __syncthreads();

    unsigned long long KT = 0ull;
    if (keptTotal > MAXDET) {
        if (tid == 0) { s_pre = 0ull; s_target = MAXDET; }
        __syncthreads();
        for (int shift = 56; shift >= 0; shift -= 8) {
            if (tid < 256) hist[tid] = 0;
            __syncthreads();
            unsigned long long pre = s_pre;
            for (int m = tid; m < C; m += 1024) {
                if (kem[m]) {
                    unsigned long long k = keys[m];
                    bool ok = (shift == 56) ||
                              ((k >> (shift + 8)) == (pre >> (shift + 8)));
                    if (ok) atomicAdd(&hist[(int)((k >> shift) & 0xFF)], 1);
                }
            }
            __syncthreads();
            if (wid == 0) {
                int s8 = 0;
                #pragma unroll
                for (int q = 0; q < 8; q++) s8 += hist[lane * 8 + q];
                int suf = s8;
                #pragma unroll
                for (int o = 1; o < 32; o <<= 1) {
                    int v = __shfl_down_sync(FULLM, suf, o);
                    if (lane + o < 32) suf += v;
                }
                int sufnext = suf - s8;
                int target = s_target;
                if (suf >= target && sufnext < target) {
                    int cacc = sufnext;
                    for (int q = 7; q >= 0; q--) {
                        int h = hist[lane * 8 + q];
                        cacc += h;
                        if (cacc >= target) {
                            s_pre = pre | ((unsigned long long)(lane * 8 + q) << shift);
                            s_target = target - (cacc - h);
                            break;
                        }
                    }
                }
            }
            __syncthreads();
        }
        KT = s_pre;   // exact 1000th-largest kept key (keys unique)
    }

    // prefix over pick flags (m-ascending)
    int t0 = tid * 4;
    int k0 = (kem[t0]     && keys[t0]     >= KT) ? 1 : 0;
    int k1 = (kem[t0 + 1] && keys[t0 + 1] >= KT) ? 1 : 0;
    int k2 = (kem[t0 + 2] && keys[t0 + 2] >= KT) ? 1 : 0;
    int k3 = (kem[t0 + 3] && keys[t0 + 3] >= KT) ? 1 : 0;
    int sum4 = k0 + k1 + k2 + k3;
    int sc = sum4;
    for (int o = 1; o < 32; o <<= 1) {
        int v = __shfl_up_sync(FULLM, sc, o);
        if (lane >= o) sc += v;
    }
    if (lane == 31) wsum[wid] = sc;
    __syncthreads();
    if (wid == 0) {
        int w = wsum[lane];
        for (int o = 1; o < 32; o <<= 1) {
            int v = __shfl_up_sync(FULLM, w, o);
            if (lane >= o) w += v;
        }
        wsum[lane] = w;
        if (lane == 31) s_total = w;
    }
    __syncthreads();
    int base2 = (wid ? wsum[wid - 1] : 0) + (sc - sum4);
    int p0 = base2 + k0, p1 = p0 + k1, p2 = p1 + k2, p3 = p2 + k3;
    if (k0 && p0 <= MAXDET) picks[p0 - 1] = t0;
    if (k1 && p1 <= MAXDET) picks[p1 - 1] = t0 + 1;
    if (k2 && p2 <= MAXDET) picks[p2 - 1] = t0 + 2;
    if (k3 && p3 <= MAXDET) picks[p3 - 1] = t0 + 3;
    __syncthreads();

    int cnt = s_total; if (cnt > MAXDET) cnt = MAXDET;
    if (tid == 0) g_cnt[b] = cnt;
    for (int t = tid; t < cnt; t += 1024)
        g_pickrow[b * MAXDET + t] = g_A16[b * KNMS + picks[t]];  // A[m] pick quirk
}

// ---------------- K5: accumulation partials (8 blocks/image, warp-per-pick) ----------------
__global__ void k_acc(const float* __restrict__ p) {
    int b = blockIdx.y;
    int part = blockIdx.x;
    int tid = threadIdx.x, lane = tid & 31, wid = tid >> 5;
    __shared__ float s_out[NCL];
    if (tid < NCL) s_out[tid] = 0.0f;
    __syncthreads();

    int cnt = g_cnt[b];
    int gw = part * 8 + wid;   // 0..63

    float a0 = 0.0f, a1 = 0.0f, a2 = 0.0f;
    int t = gw;
    float obj = 0.0f, c0 = 0.0f, c1 = 0.0f, c2 = 0.0f;
    if (t < cnt) {
        const float* pr = p + ((size_t)b * NN + g_pickrow[b * MAXDET + t]) * NCH;
        obj = pr[4];
        c0 = pr[5 + lane];
        c1 = pr[37 + lane];
        c2 = (lane < 16) ? pr[69 + lane] : 0.0f;
    }
    while (t < cnt) {
        int t2 = t + 64;
        float obj2 = 0.0f, d0 = 0.0f, d1 = 0.0f, d2 = 0.0f;
        if (t2 < cnt) {
            const float* pr2 = p + ((size_t)b * NN + g_pickrow[b * MAXDET + t2]) * NCH;
            obj2 = pr2[4];
            d0 = pr2[5 + lane];
            d1 = pr2[37 + lane];
            d2 = (lane < 16) ? pr2[69 + lane] : 0.0f;
        }
        a0 += obj * c0;
        a1 += obj * c1;
        a2 += obj * c2;
        obj = obj2; c0 = d0; c1 = d1; c2 = d2;
        t = t2;
    }
    atomicAdd(&s_out[lane], a0);
    atomicAdd(&s_out[32 + lane], a1);
    if (lane < 16) atomicAdd(&s_out[64 + lane], a2);
    __syncthreads();
    if (tid < NCL) g_part[(b * NPART + part) * NCL + tid] = s_out[tid];
}

// ---------------- K6: deterministic partial reduce ----------------
__global__ void k_reduce(float* __restrict__ out) {
    int b = blockIdx.x;
    int c = threadIdx.x;
    float acc = 0.0f;
    #pragma unroll
    for (int q = 0; q < NPART; q++)
        acc += g_part[(b * NPART + q) * NCL + c];
    out[b * NCL + c] = acc;
}

// ---------------- launcher ----------------
extern "C" void kernel_launch(void* const* d_in, const int* in_sizes, int n_in,
                              void* d_out, int out_size) {
    const float* p = (const float*)d_in[0];
    float* out = (float*)d_out;

    k_all<<<dim3((NN + RPB - 1) / RPB, BB), RPB>>>(p);
    k_prep<<<BB, 1024>>>();
    cudaFuncSetAttribute(k_greedy, cudaFuncAttributeMaxDynamicSharedMemorySize, 65536);
    k_greedy<<<dim3(10, BB), 256, 65536>>>();
    cudaFuncSetAttribute(k_select, cudaFuncAttributeMaxDynamicSharedMemorySize, 40960);
    k_select<<<BB, 1024, 40960>>>();
    k_acc<<<dim3(NPART, BB), 256>>>(p);
    k_reduce<<<BB, NCL>>>(out);
}

// round 10
// speedup vs baseline: 1.1418x; 1.1418x over previous
#include <cuda_runtime.h>
#include <cstdint>

#define BB   32
#define NN   25200
#define NCH  85
#define NCL  80
#define KNMS 4096
#define CONF_T 0.25f
#define IOU_T  0.45f
#define MAXDET 1000
#define MAXWH  7680.0f
#define CLCAP 256
#define FULLM 0xffffffffu
#define RPB  256           // rows per k_all block (= 8 mask words)
#define NWORDS 788         // ceil(25200/32)

__device__ unsigned g_maskA[BB * NWORDS];    // xc bitmask
__device__ unsigned g_maskW[BB * NWORDS];    // w bitmask
__device__ float         g_conf[BB * NN];    // by row (w rows)
__device__ unsigned char g_j[BB * NN];       // by row (w rows)
__device__ float4        g_cbox[BB * NN];    // by row (w rows)

__device__ unsigned short g_A16[BB * KNMS];       // xc rank -> row
__device__ unsigned long long g_keys[BB * KNMS];  // by w-rank m
__device__ float4        g_box[BB * KNMS];        // by w-rank m
__device__ unsigned short g_cls[BB * NCL * CLCAP];// per-class m lists
__device__ int           g_clsn[BB * NCL];
__device__ unsigned char g_kem[BB * KNMS];        // kept flag by m
__device__ int           g_kept[BB];
__device__ int           g_cw[BB];                // C per image

// ---------------- K1: full-grid row scan + candidate scoring -> bitmasks ----------------
__global__ void k_all(const float* __restrict__ p) {
    int b = blockIdx.y;
    int r0 = blockIdx.x * RPB;
    int tid = threadIdx.x, lane = tid & 31, wid = tid >> 5;
    __shared__ unsigned short wl[RPB];
    __shared__ unsigned sm_wmask[RPB / 32];
    __shared__ int s_cnt;
    if (tid == 0) s_cnt = 0;
    if (tid < RPB / 32) sm_wmask[tid] = 0u;
    __syncthreads();

    int row = r0 + tid;
    bool xc = false;
    if (row < NN) {
        float obj = p[((size_t)b * NN + row) * NCH + 4];
        xc = obj > CONF_T;
    }
    unsigned bal = __ballot_sync(FULLM, xc);
    if (lane == 0 && row < NN)
        g_maskA[b * NWORDS + (row >> 5)] = bal;
    int base = 0;
    if (lane == 0 && bal) base = atomicAdd(&s_cnt, __popc(bal));
    base = __shfl_sync(FULLM, base, 0);
    if (xc) wl[base + __popc(bal & ((1u << lane) - 1u))] = (unsigned short)row;
    __syncthreads();

    int cnt = s_cnt;
    for (int k = wid; k < cnt; k += 8) {
        int r = wl[k];
        const float* pr = p + ((size_t)b * NN + r) * NCH;
        float v0 = pr[lane];
        float v1 = pr[lane + 32];
        float v2 = (lane < 21) ? pr[lane + 64] : 0.0f;
        float obj = __shfl_sync(FULLM, v0, 4);

        float bv = -3.4e38f; int bi = 1 << 20;
        if (lane >= 5) { bv = obj * v0; bi = lane - 5; }          // cls 0..26
        { float sc = obj * v1; int i1 = lane + 27;                // cls 27..58
          if (sc > bv) { bv = sc; bi = i1; } }
        if (lane < 21) { float sc = obj * v2; int i2 = lane + 59; // cls 59..79
          if (sc > bv) { bv = sc; bi = i2; } }
        for (int off = 16; off; off >>= 1) {
            float ov = __shfl_xor_sync(FULLM, bv, off);
            int   oi = __shfl_xor_sync(FULLM, bi, off);
            if (ov > bv || (ov == bv && oi < bi)) { bv = ov; bi = oi; }
        }
        float x  = __shfl_sync(FULLM, v0, 0);
        float y  = __shfl_sync(FULLM, v0, 1);
        float ww = __shfl_sync(FULLM, v0, 2);
        float hh = __shfl_sync(FULLM, v0, 3);
        if (lane == 0 && bv > CONF_T) {
            atomicOr(&sm_wmask[(r - r0) >> 5], 1u << (r & 31));
            g_conf[b * NN + r] = bv;
            g_j[b * NN + r] = (unsigned char)bi;
            float off = (float)bi * MAXWH;
            float hw = __fmul_rn(ww, 0.5f);
            float hv = __fmul_rn(hh, 0.5f);
            float4 bx;
            bx.x = __fadd_rn(__fsub_rn(x, hw), off);
            bx.y = __fadd_rn(__fsub_rn(y, hv), off);
            bx.z = __fadd_rn(__fadd_rn(x, hw), off);
            bx.w = __fadd_rn(__fadd_rn(y, hv), off);
            g_cbox[b * NN + r] = bx;
        }
    }
    __syncthreads();
    if (tid < RPB / 32) {
        int word = (r0 >> 5) + tid;
        if (word < NWORDS && word * 32 < NN)
            g_maskW[b * NWORDS + word] = sm_wmask[tid];
    }
}

// ---------------- K2: per-image prep: scan + scatter + class bucketing ----------------
__global__ void k_prep() {
    int b = blockIdx.x;
    int tid = threadIdx.x, lane = tid & 31, wid = tid >> 5;
    __shared__ int wsum[32];
    __shared__ int s_total;
    __shared__ int clsCnt[NCL];

    unsigned wa = 0, wb = 0;
    if (tid < NWORDS) {
        wa = g_maskA[b * NWORDS + tid];
        wb = g_maskW[b * NWORDS + tid];
    }
    if (tid < NCL) clsCnt[tid] = 0;
    if (tid == 0) g_kept[b] = 0;
    ((int*)(g_kem + (size_t)b * KNMS))[tid] = 0;
    int pk = __popc(wa) | (__popc(wb) << 16);
    int s = pk;
    for (int o = 1; o < 32; o <<= 1) {
        int v = __shfl_up_sync(FULLM, s, o);
        if (lane >= o) s += v;
    }
    if (lane == 31) wsum[wid] = s;
    __syncthreads();
    if (wid == 0) {
        int w = wsum[lane];
        for (int o = 1; o < 32; o <<= 1) {
            int v = __shfl_up_sync(FULLM, w, o);
            if (lane >= o) w += v;
        }
        wsum[lane] = w;
        if (lane == 31) s_total = w;
    }
    __syncthreads();
    int excl = (wid ? wsum[wid - 1] : 0) + s - pk;
    {
        int pa = excl & 0xffff;
        unsigned w = wa;
        while (w) {
            int bit = __ffs(w) - 1; w &= w - 1;
            if (pa < KNMS) g_A16[b * KNMS + pa] = (unsigned short)(tid * 32 + bit);
            pa++;
        }
        int pw = excl >> 16;
        w = wb;
        while (w) {
            int bit = __ffs(w) - 1; w &= w - 1;
            int r = tid * 32 + bit;
            if (pw < KNMS) {
                g_keys[b * KNMS + pw] =
                    ((unsigned long long)__float_as_uint(g_conf[b * NN + r]) << 32)
                  | (unsigned long long)(~(unsigned)pw);
                g_box[b * KNMS + pw] = g_cbox[b * NN + r];
                int c = g_j[b * NN + r];
                int slot = atomicAdd(&clsCnt[c], 1);
                if (slot < CLCAP)
                    g_cls[((size_t)b * NCL + c) * CLCAP + slot] = (unsigned short)pw;
            }
            pw++;
        }
    }
    __syncthreads();
    if (tid == 0) {
        int C = s_total >> 16; if (C > KNMS) C = KNMS;
        g_cw[b] = C;
    }
    if (tid < NCL) {
        int n = clsCnt[tid]; if (n > CLCAP) n = CLCAP;
        g_clsn[b * NCL + tid] = n;
    }
}

// ---------------- K3: one warp per (image, class) greedy NMS ----------------
// Classes never overlap (offset 7680 >> box extent): cross-class IoU == 0.
__global__ void k_greedy() {
    int b = blockIdx.y;
    int tid = threadIdx.x, lane = tid & 31, wid = tid >> 5;
    int c = blockIdx.x * 8 + wid;

    extern __shared__ char smem[];
    char* wbase = smem + wid * 8192;
    unsigned long long* sk = (unsigned long long*)(wbase + 0);    // 256*8
    float4*         sbx = (float4*)(wbase + 2048);                // 256*16
    float*          sar = (float*)(wbase + 6144);                 // 256*4
    unsigned short* sml = (unsigned short*)(wbase + 7168);        // 256*2
    unsigned short* dst = (unsigned short*)(wbase + 7680);        // 256*2

    if (c >= NCL) return;
    int n = g_clsn[b * NCL + c];
    if (n == 0) return;

    for (int e = lane; e < n; e += 32) {
        int m = g_cls[((size_t)b * NCL + c) * CLCAP + e];
        sml[e] = (unsigned short)m;
        sk[e] = g_keys[b * KNMS + m];
        float4 bx = g_box[b * KNMS + m];
        sbx[e] = bx;
        sar[e] = __fmul_rn(__fsub_rn(bx.z, bx.x), __fsub_rn(bx.w, bx.y));
    }
    __syncwarp();
    // rank-sort descending by key (keys unique -> perfect permutation)
    for (int e = lane; e < n; e += 32) {
        unsigned long long ke = sk[e];
        int r = 0;
        for (int f = 0; f < n; f++) r += (sk[f] > ke) ? 1 : 0;
        dst[r] = (unsigned short)e;
    }
    __syncwarp();

    int kcnt = 0;
    unsigned rm = 0;   // removed: entry e owned by lane e&31, bit e>>5
    for (int i = 0; i < n; i++) {
        unsigned rmi = __shfl_sync(FULLM, rm, i & 31);
        if ((rmi >> (i >> 5)) & 1u) continue;   // uniform
        int mi = dst[i];
        kcnt++;
        if (lane == 0) g_kem[b * KNMS + sml[mi]] = 1;
        float4 bi4 = sbx[mi];
        float ba = sar[mi];
        for (int k = 0, e = lane; e < n; k++, e += 32) {
            if (e > i && !((rm >> k) & 1u)) {
                int mj = dst[e];
                float4 bj = sbx[mj];
                float iw = __fsub_rn(fminf(bj.z, bi4.z), fmaxf(bj.x, bi4.x));
                float ih = __fsub_rn(fminf(bj.w, bi4.w), fmaxf(bj.y, bi4.y));
                float inter = __fmul_rn(fmaxf(iw, 0.0f), fmaxf(ih, 0.0f));
                float denom = __fsub_rn(__fadd_rn(sar[mj], ba), inter);
                if (__fdiv_rn(inter, denom) > IOU_T) rm |= (1u << k);
            }
        }
        __syncwarp();
    }
    if (lane == 0 && kcnt) atomicAdd(&g_kept[b], kcnt);
}

// ---------------- K4: 2-sweep exact select + cap + pipelined accumulation ----------------
__global__ void k_final(const float* __restrict__ p, float* __restrict__ out) {
    int b = blockIdx.x;
    int tid = threadIdx.x, lane = tid & 31, wid = tid >> 5;

    extern __shared__ char smem[];
    unsigned long long* ck   = (unsigned long long*)(smem + 0);      // 32KB compact keys by m
    unsigned long long* list = (unsigned long long*)(smem + 32768);  // 32KB bin members
    int*            picks = (int*)(smem + 65536);                    // 4KB
    unsigned short* srow  = (unsigned short*)(smem + 69632);         // 2KB
    unsigned char*  kem   = (unsigned char*)(smem + 71680);          // 4KB
    __shared__ int hist[1024];
    __shared__ int wsum[32];
    __shared__ int s_total, s_target, s_bin, s_nlist;
    __shared__ unsigned long long s_KT;
    __shared__ float s_out[NCL];

    int C = g_cw[b];
    int keptTotal = g_kept[b];
    // stage compact keys: conf in (0.25, 1] (obj,cls <= 1 by construction), so
    // conf_bits - 0x3E800000 fits 25 bits; low 12 bits of ~m equal 4095-m (m<4096).
    // ck = (cb<<12)|(4095-m) is order-isomorphic to (conf_bits<<32)|~m.
    for (int t = tid; t < KNMS; t += 1024) {
        if (t < C) {
            unsigned long long key = g_keys[b * KNMS + t];
            unsigned cb = (unsigned)(key >> 32) - 0x3E800000u;
            ck[t] = ((unsigned long long)cb << 12) | (unsigned)(key & 0xFFFull);
            kem[t] = g_kem[b * KNMS + t];
        } else {
            ck[t] = 0ull;
            kem[t] = 0;
        }
    }
    if (tid < NCL) s_out[tid] = 0.0f;
    if (tid < 1024) hist[tid] = 0;
    if (tid == 0) { s_nlist = 0; s_KT = 0ull; }
    __syncthreads();

    unsigned long long KT = 0ull;
    if (keptTotal > MAXDET) {
        // sweep 1: 1024-bin histogram on ck>>27
        for (int m = tid; m < C; m += 1024)
            if (kem[m]) atomicAdd(&hist[(int)(ck[m] >> 27)], 1);
        __syncthreads();
        // find threshold bin (descending) + residual rank t'
        if (wid == 0) {
            int s32 = 0;
            #pragma unroll
            for (int q = 0; q < 32; q++) s32 += hist[lane * 32 + q];
            int suf = s32;
            #pragma unroll
            for (int o = 1; o < 32; o <<= 1) {
                int v = __shfl_down_sync(FULLM, suf, o);
                if (lane + o < 32) suf += v;
            }
            int sufnext = suf - s32;   // bins in lanes > this one (higher bins)
            if (suf >= MAXDET && sufnext < MAXDET) {
                int cacc = sufnext;
                for (int q = 31; q >= 0; q--) {
                    int h = hist[lane * 32 + q];
                    cacc += h;
                    if (cacc >= MAXDET) {
                        s_bin = lane * 32 + q;
                        s_target = MAXDET - (cacc - h);   // t'-th largest within bin
                        break;
                    }
                }
            }
        }
        __syncthreads();
        // sweep 2: collect threshold-bin members
        int B = s_bin;
        for (int m = tid; m < C; m += 1024) {
            if (kem[m] && (int)(ck[m] >> 27) == B) {
                int slot = atomicAdd(&s_nlist, 1);
                list[slot] = ck[m];
            }
        }
        __syncthreads();
        // block-wide rank to find exact t'-th largest in bin (keys unique)
        int nlist = s_nlist;
        int tprime = s_target;
        for (int e = tid; e < nlist; e += 1024) {
            unsigned long long ke = list[e];
            int r = 0;
            for (int f = 0; f < nlist; f++) r += (list[f] > ke) ? 1 : 0;
            if (r == tprime - 1) s_KT = ke;
        }
        __syncthreads();
        KT = s_KT;
    }

    // prefix over pick flags (m-ascending)
    int t0 = tid * 4;
    int k0 = (kem[t0]     && ck[t0]     >= KT) ? 1 : 0;
    int k1 = (kem[t0 + 1] && ck[t0 + 1] >= KT) ? 1 : 0;
    int k2 = (kem[t0 + 2] && ck[t0 + 2] >= KT) ? 1 : 0;
    int k3 = (kem[t0 + 3] && ck[t0 + 3] >= KT) ? 1 : 0;
    int sum4 = k0 + k1 + k2 + k3;
    int sc = sum4;
    for (int o = 1; o < 32; o <<= 1) {
        int v = __shfl_up_sync(FULLM, sc, o);
        if (lane >= o) sc += v;
    }
    if (lane == 31) wsum[wid] = sc;
    __syncthreads();
    if (wid == 0) {
        int w = wsum[lane];
        for (int o = 1; o < 32; o <<= 1) {
            int v = __shfl_up_sync(FULLM, w, o);
            if (lane >= o) w += v;
        }
        wsum[lane] = w;
        if (lane == 31) s_total = w;
    }
    __syncthreads();
    int base2 = (wid ? wsum[wid - 1] : 0) + (sc - sum4);
    int p0 = base2 + k0, p1 = p0 + k1, p2 = p1 + k2, p3 = p2 + k3;
    if (k0 && p0 <= MAXDET) picks[p0 - 1] = t0;
    if (k1 && p1 <= MAXDET) picks[p1 - 1] = t0 + 1;
    if (k2 && p2 <= MAXDET) picks[p2 - 1] = t0 + 2;
    if (k3 && p3 <= MAXDET) picks[p3 - 1] = t0 + 3;
    __syncthreads();

    int cnt = s_total; if (cnt > MAXDET) cnt = MAXDET;
    // stage pick rows (reference's A[m] quirk)
    for (int t = tid; t < cnt; t += 1024)
        srow[t] = g_A16[b * KNMS + picks[t]];
    __syncthreads();

    // accumulation: warp per pick, 4 independent picks per iteration (MLP ~16)
    float a0 = 0.0f, a1 = 0.0f, a2 = 0.0f;
    for (int k = wid; k < cnt; k += 128) {
        int ta = k, tb2 = k + 32, tc = k + 64, td = k + 96;
        float oA = 0.f, cA0 = 0.f, cA1 = 0.f, cA2 = 0.f;
        float oB = 0.f, cB0 = 0.f, cB1 = 0.f, cB2 = 0.f;
        float oC = 0.f, cC0 = 0.f, cC1 = 0.f, cC2 = 0.f;
        float oD = 0.f, cD0 = 0.f, cD1 = 0.f, cD2 = 0.f;
        {
            const float* pr = p + ((size_t)b * NN + srow[ta]) * NCH;
            oA = pr[4]; cA0 = pr[5 + lane]; cA1 = pr[37 + lane];
            cA2 = (lane < 16) ? pr[69 + lane] : 0.0f;
        }
        if (tb2 < cnt) {
            const float* pr = p + ((size_t)b * NN + srow[tb2]) * NCH;
            oB = pr[4]; cB0 = pr[5 + lane]; cB1 = pr[37 + lane];
            cB2 = (lane < 16) ? pr[69 + lane] : 0.0f;
        }
        if (tc < cnt) {
            const float* pr = p + ((size_t)b * NN + srow[tc]) * NCH;
            oC = pr[4]; cC0 = pr[5 + lane]; cC1 = pr[37 + lane];
            cC2 = (lane < 16) ? pr[69 + lane] : 0.0f;
        }
        if (td < cnt) {
            const float* pr = p + ((size_t)b * NN + srow[td]) * NCH;
            oD = pr[4]; cD0 = pr[5 + lane]; cD1 = pr[37 + lane];
            cD2 = (lane < 16) ? pr[69 + lane] : 0.0f;
        }
        a0 += oA * cA0 + oB * cB0 + oC * cC0 + oD * cD0;
        a1 += oA * cA1 + oB * cB1 + oC * cC1 + oD * cD1;
        a2 += oA * cA2 + oB * cB2 + oC * cC2 + oD * cD2;
    }
    atomicAdd(&s_out[lane], a0);
    atomicAdd(&s_out[32 + lane], a1);
    if (lane < 16) atomicAdd(&s_out[64 + lane], a2);
    __syncthreads();
    if (tid < NCL) out[b * NCL + tid] = s_out[tid];
}

// ---------------- launcher ----------------
extern "C" void kernel_launch(void* const* d_in, const int* in_sizes, int n_in,
                              void* d_out, int out_size) {
    const float* p = (const float*)d_in[0];
    float* out = (float*)d_out;

    k_all<<<dim3((NN + RPB - 1) / RPB, BB), RPB>>>(p);
    k_prep<<<BB, 1024>>>();
    cudaFuncSetAttribute(k_greedy, cudaFuncAttributeMaxDynamicSharedMemorySize, 65536);
    k_greedy<<<dim3(10, BB), 256, 65536>>>();
    cudaFuncSetAttribute(k_final, cudaFuncAttributeMaxDynamicSharedMemorySize, 75776);
    k_final<<<BB, 1024, 75776>>>(p, out);
}